// round 16
// baseline (speedup 1.0000x reference)
#include <cuda_runtime.h>
#include <cstdint>
#include <math.h>

// ---------------------------------------------------------------------------
// Problem constants
// ---------------------------------------------------------------------------
namespace {
constexpr int CB     = 2;
constexpr int CT     = 8;
constexpr int CS     = 256;
constexpr int CNTOK  = CT * CS;      // 2048
constexpr int CROWS  = CB * CNTOK;   // 4096
constexpr int CC     = 1152;
constexpr int CH     = 16;
constexpr int CHD    = 72;
constexpr int CM     = 224;
constexpr int CKVR   = CB * CM;      // 448
constexpr int CDH    = 4608;
constexpr int KC     = 504;          // Eigen kc panel (aarch64 L1=32KB default)
constexpr int NROWS  = CROWS * CH;   // 65536 attention rows
}
#define QSCALE_F  0.117851130664348602294921875f   /* fl32(72**-0.5) */
#define SQ2OPI_F  0.797884583473205566406250f      /* fl32(np.sqrt(2/np.pi)) */

// ---------------------------------------------------------------------------
// Scratch
// ---------------------------------------------------------------------------
__device__ float g_xm[CROWS * CC];
__device__ float g_qkv[CROWS * 3 * CC];
__device__ float g_tmp[CROWS * CC];
__device__ float g_crossq[CROWS * CC];
__device__ float g_kv[CKVR * 2 * CC];
__device__ float g_h[CROWS * CDH];
__device__ float g_x[CROWS * CC];
__device__ float g_sc[(size_t)NROWS * CKVR];      // scores, TRANSPOSED [k][row]
__device__ int   g_q8[CROWS * CDH / 4];
__device__ float g_srow[CROWS];
__device__ int   g_qsum[CROWS];
__device__ int   g_wq8 [CC * CC / 4];
__device__ int   g_wcp8[CC * CC / 4];
__device__ int   g_wf18[CDH * CC / 4];
__device__ int   g_wf28[CC * CDH / 4];

// ---------------------------------------------------------------------------
// XLA:CPU bit-mimicry helpers
// ---------------------------------------------------------------------------
__device__ __forceinline__ float xla_expf(float x) {
    float xc = fminf(x, 88.3762626647950f);
    xc = fmaxf(xc, -88.3762626647949f);
    float fx = __fadd_rn(__fmul_rn(xc, 1.44269504088896341f), 0.5f);
    fx = floorf(fx);
    float tmp = __fmul_rn(fx, 0.693359375f);
    float z2  = __fmul_rn(fx, -2.12194440e-4f);
    float xr  = __fsub_rn(xc, tmp);
    xr = __fsub_rn(xr, z2);
    float zz = __fmul_rn(xr, xr);
    float y = 1.9875691500E-4f;
    y = __fadd_rn(__fmul_rn(y, xr), 1.3981999507E-3f);
    y = __fadd_rn(__fmul_rn(y, xr), 8.3334519073E-3f);
    y = __fadd_rn(__fmul_rn(y, xr), 4.1665795894E-2f);
    y = __fadd_rn(__fmul_rn(y, xr), 1.6666665459E-1f);
    y = __fadd_rn(__fmul_rn(y, xr), 5.0000001201E-1f);
    y = __fadd_rn(__fmul_rn(y, zz), xr);
    y = __fadd_rn(y, 1.0f);
    int n = (int)fx;
    float p2n = __uint_as_float((unsigned)(n + 127) << 23);
    return __fmul_rn(y, p2n);
}

__device__ __forceinline__ float xla_tanh(float x) {
    if (fabsf(x) < 0.0004f) return x;
    float xc = fminf(fmaxf(x, -7.90531110763549805f), 7.90531110763549805f);
    float x2 = __fmul_rn(xc, xc);
    float p = -2.76076847742355e-16f;
    p = __fadd_rn(__fmul_rn(x2, p),  2.00018790482477e-13f);
    p = __fadd_rn(__fmul_rn(x2, p), -8.60467152213735e-11f);
    p = __fadd_rn(__fmul_rn(x2, p),  5.12229709037114e-08f);
    p = __fadd_rn(__fmul_rn(x2, p),  1.48572235717979e-05f);
    p = __fadd_rn(__fmul_rn(x2, p),  6.37261928875436e-04f);
    p = __fadd_rn(__fmul_rn(x2, p),  4.89352455891786e-03f);
    float num = __fmul_rn(xc, p);
    float q = __fadd_rn(__fmul_rn(x2, 1.19825839466702e-06f), 1.18534705686654e-04f);
    q = __fadd_rn(__fmul_rn(x2, q), 2.26843463243900e-03f);
    q = __fadd_rn(__fmul_rn(x2, q), 4.89352518554385e-03f);
    return __fdiv_rn(num, q);
}

__device__ __forceinline__ float gelu_xla(float v) {
    float v2 = __fmul_rn(v, v);
    float v3 = __fmul_rn(v2, v);
    float inner = __fadd_rn(v, __fmul_rn(0.044715f, v3));
    float u = __fmul_rn(SQ2OPI_F, inner);
    float th = xla_tanh(u);
    return __fmul_rn(__fmul_rn(0.5f, v), __fadd_rn(1.0f, th));
}

__device__ __forceinline__ float combine4p(const float* c) {
    return __fadd_rn(__fadd_rn(c[0], c[1]), __fadd_rn(c[2], c[3]));
}

__device__ __forceinline__ float warpMax(float v) {
    #pragma unroll
    for (int o = 16; o; o >>= 1) v = fmaxf(v, __shfl_xor_sync(0xffffffffu, v, o));
    return v;
}
__device__ __forceinline__ double warpSumD(double v) {
    #pragma unroll
    for (int o = 16; o; o >>= 1) v += __shfl_xor_sync(0xffffffffu, v, o);
    return v;
}
__device__ __forceinline__ int warpSumI(int v) {
    #pragma unroll
    for (int o = 16; o; o >>= 1) v += __shfl_xor_sync(0xffffffffu, v, o);
    return v;
}

__device__ __forceinline__ void mma_s8(
    int& d0, int& d1, int& d2, int& d3,
    int a0, int a1, int a2, int a3, int b0, int b1)
{
    asm volatile(
        "mma.sync.aligned.m16n8k32.row.col.s32.s8.s8.s32 "
        "{%0,%1,%2,%3}, {%4,%5,%6,%7}, {%8,%9}, {%0,%1,%2,%3};"
        : "+r"(d0), "+r"(d1), "+r"(d2), "+r"(d3)
        : "r"(a0), "r"(a1), "r"(a2), "r"(a3), "r"(b0), "r"(b1));
}

// ---------------------------------------------------------------------------
// Pack int32-widened int8 weights into packed int8 words
// ---------------------------------------------------------------------------
__global__ void __launch_bounds__(256) pack_i8_k(
    const int4* __restrict__ W32, int* __restrict__ W8, int n4)
{
    int i = blockIdx.x * 256 + threadIdx.x;
    if (i < n4) {
        int4 v = W32[i];
        unsigned w = (unsigned)(v.x & 0xff)
                   | ((unsigned)(v.y & 0xff) << 8)
                   | ((unsigned)(v.z & 0xff) << 16)
                   | ((unsigned)(v.w & 0xff) << 24);
        W8[i] = (int)w;
    }
}

// ---------------------------------------------------------------------------
// LayerNorm + adaLN modulate — fp64-exact stats, fp32 modulate (unfused).
// ---------------------------------------------------------------------------
__global__ void __launch_bounds__(256) ln_mod_k(
    const float* __restrict__ X, float* __restrict__ out,
    const float* __restrict__ t, const float* __restrict__ sst,
    int shidx, int scidx)
{
    const int row = blockIdx.x, tid = threadIdx.x;
    const int lane = tid & 31, wp = tid >> 5;
    const int b = row / CNTOK;
    const float* xr = X + (size_t)row * CC;
    __shared__ double smA[8];
    __shared__ float stats[2];

    double s1 = 0.0;
    for (int i = tid; i < CC; i += 256) s1 += (double)xr[i];
    s1 = warpSumD(s1);
    if (lane == 0) smA[wp] = s1;
    __syncthreads();
    if (tid == 0) {
        double a = 0.0;
        #pragma unroll
        for (int i = 0; i < 8; i++) a += smA[i];
        stats[0] = (float)(a / 1152.0);
    }
    __syncthreads();
    const float meanf = stats[0];

    double s2 = 0.0;
    for (int i = tid; i < CC; i += 256) {
        double d = (double)xr[i] - (double)meanf;
        s2 += d * d;
    }
    s2 = warpSumD(s2);
    if (lane == 0) smA[wp] = s2;
    __syncthreads();
    if (tid == 0) {
        double c2 = 0.0;
        #pragma unroll
        for (int i = 0; i < 8; i++) c2 += smA[i];
        float varf = (float)(c2 / 1152.0);
        stats[1] = __fdiv_rn(1.0f, __fsqrt_rn(__fadd_rn(varf, 1e-6f)));
    }
    __syncthreads();
    const float rstd = stats[1];
    const float* tb = t + (size_t)b * 6 * CC;
    for (int i = tid; i < CC; i += 256) {
        float sc = __fadd_rn(1.0f, __fadd_rn(sst[scidx * CC + i], tb[scidx * CC + i]));
        float sh = __fadd_rn(sst[shidx * CC + i], tb[shidx * CC + i]);
        float ln = __fmul_rn(__fsub_rn(xr[i], meanf), rstd);
        out[(size_t)row * CC + i] = __fadd_rn(__fmul_rn(ln, sc), sh);   // unfused
    }
}

// ---------------------------------------------------------------------------
// fp32 GEMM — 128x64 tile, 8x4 microtile, Eigen kc=504 panel folds.
// ---------------------------------------------------------------------------
template<int MODE>
__global__ void __launch_bounds__(256) gemm_f32_k(
    const float* __restrict__ A, const float* __restrict__ W,
    const float* __restrict__ bias, float* __restrict__ out,
    int Nn, int Kk, int Mrows,
    const float* __restrict__ xsrc, const float* __restrict__ t,
    const float* __restrict__ sst, int gidx)
{
    __shared__ float As[16][128];
    __shared__ float Ws[16][64];
    const int tid = threadIdx.x;
    const int tx = tid & 15;
    const int ty = tid >> 4;
    const int rowbase = blockIdx.y * 128;
    const int colbase = blockIdx.x * 64;
    const int lr = tid >> 1;
    const int lk = (tid & 1) * 8;
    const int wr = tid >> 2;
    const int wk = (tid & 3) * 4;
    const int ar_g = (rowbase + lr < Mrows) ? (rowbase + lr) : (Mrows - 1);
    const float* Ap = A + (size_t)ar_g * Kk;
    const float* Wp = W + (size_t)(colbase + wr) * Kk;
    float acc[8][4] = {};
    float tot[8][4] = {};

    for (int k0 = 0; k0 < Kk; k0 += 16) {
        float4 a0 = *(const float4*)(Ap + k0 + lk);
        float4 a1 = *(const float4*)(Ap + k0 + lk + 4);
        float4 wv = *(const float4*)(Wp + k0 + wk);
        As[lk + 0][lr] = a0.x; As[lk + 1][lr] = a0.y;
        As[lk + 2][lr] = a0.z; As[lk + 3][lr] = a0.w;
        As[lk + 4][lr] = a1.x; As[lk + 5][lr] = a1.y;
        As[lk + 6][lr] = a1.z; As[lk + 7][lr] = a1.w;
        Ws[wk + 0][wr] = wv.x; Ws[wk + 1][wr] = wv.y;
        Ws[wk + 2][wr] = wv.z; Ws[wk + 3][wr] = wv.w;
        __syncthreads();
        #pragma unroll
        for (int kk = 0; kk < 16; kk++) {
            int kg = k0 + kk;
            if (kg == KC || kg == 2 * KC) {      // Eigen panel boundary
                #pragma unroll
                for (int i = 0; i < 8; i++)
                    #pragma unroll
                    for (int j = 0; j < 4; j++) {
                        tot[i][j] = __fadd_rn(tot[i][j], acc[i][j]);
                        acc[i][j] = 0.f;
                    }
            }
            float4 aa0 = *(const float4*)&As[kk][ty * 8];
            float4 aa1 = *(const float4*)&As[kk][ty * 8 + 4];
            float4 ww  = *(const float4*)&Ws[kk][tx * 4];
            float ar[8] = {aa0.x, aa0.y, aa0.z, aa0.w, aa1.x, aa1.y, aa1.z, aa1.w};
            float wr4[4] = {ww.x, ww.y, ww.z, ww.w};
            #pragma unroll
            for (int i = 0; i < 8; i++)
                #pragma unroll
                for (int j = 0; j < 4; j++)
                    acc[i][j] = __fmaf_rn(ar[i], wr4[j], acc[i][j]);
        }
        __syncthreads();
    }

    #pragma unroll
    for (int i = 0; i < 8; i++) {
        const int r = rowbase + ty * 8 + i;
        if (r >= Mrows) continue;
        #pragma unroll
        for (int j = 0; j < 4; j++) {
            const int c = colbase + tx * 4 + j;
            float accv = __fadd_rn(tot[i][j], acc[i][j]);
            float v = __fadd_rn(accv, bias[c]);
            const size_t idx = (size_t)r * Nn + c;
            if (MODE == 0) {
                out[idx] = v;
            } else {
                const int b = r / CNTOK;
                float gate = __fadd_rn(sst[gidx * CC + c], t[(size_t)b * 6 * CC + gidx * CC + c]);
                out[idx] = __fadd_rn(xsrc[idx], __fmul_rn(gate, v));   // unfused
            }
        }
    }
}

// ---------------------------------------------------------------------------
// int8 GEMM via IMMA, double-buffered smem, k-step 16 words (64 int8).
// Integer accumulation — order irrelevant, exact.
// ---------------------------------------------------------------------------
template<int MODE>
__global__ void __launch_bounds__(256) gemm_i8_k(
    const int* __restrict__ A, const int* __restrict__ W,
    const float* __restrict__ srow, const int* __restrict__ qsum,
    const float* __restrict__ sw, const int* __restrict__ zw,
    const float* __restrict__ bias, float* __restrict__ outf,
    int Nn, int Kw,
    const float* __restrict__ t, const float* __restrict__ sst, int gidx,
    float* __restrict__ fout)
{
    __shared__ int As[2][64][20];   // stride 20: conflict-free (verified banks)
    __shared__ int Ws[2][64][20];
    const int tid = threadIdx.x;
    const int rowbase = blockIdx.y * 64;
    const int colbase = blockIdx.x * 64;
    const int warp = tid >> 5;
    const int lane = tid & 31;
    const int wm = warp & 3;
    const int wn = warp >> 2;
    const int g  = lane >> 2;
    const int tg = lane & 3;
    const int lr = tid >> 2;          // 0..63
    const int lq = (tid & 3) * 4;     // 0,4,8,12
    const int* ArP = A + (size_t)(rowbase + lr) * Kw + lq;
    const int* WrP = W + (size_t)(colbase + lr) * Kw + lq;

    int acc[4][4] = {};
    const int nIter = Kw / 16;

    *(int4*)&As[0][lr][lq] = *(const int4*)ArP;
    *(int4*)&Ws[0][lr][lq] = *(const int4*)WrP;
    __syncthreads();

    for (int it = 0; it < nIter; it++) {
        const int buf = it & 1;
        if (it + 1 < nIter) {
            const int kw = (it + 1) * 16;
            *(int4*)&As[buf ^ 1][lr][lq] = *(const int4*)(ArP + kw);
            *(int4*)&Ws[buf ^ 1][lr][lq] = *(const int4*)(WrP + kw);
        }
        #pragma unroll
        for (int half = 0; half < 2; half++) {
            const int o = half * 8;
            const int a0 = As[buf][wm * 16 + g    ][o + tg];
            const int a1 = As[buf][wm * 16 + g + 8][o + tg];
            const int a2 = As[buf][wm * 16 + g    ][o + 4 + tg];
            const int a3 = As[buf][wm * 16 + g + 8][o + 4 + tg];
            #pragma unroll
            for (int j = 0; j < 4; j++) {
                const int n = wn * 32 + j * 8;
                const int b0 = Ws[buf][n + g][o + tg];
                const int b1 = Ws[buf][n + g][o + 4 + tg];
                mma_s8(acc[j][0], acc[j][1], acc[j][2], acc[j][3],
                       a0, a1, a2, a3, b0, b1);
            }
        }
        __syncthreads();
    }

    #pragma unroll
    for (int j = 0; j < 4; j++) {
        #pragma unroll
        for (int f = 0; f < 4; f++) {
            const int r = rowbase + wm * 16 + g + ((f >> 1) * 8);
            const int c = colbase + wn * 32 + j * 8 + tg * 2 + (f & 1);
            const float sr = srow[r];
            const int   qr = qsum[r];
            float diff = (float)(acc[j][f] - qr * zw[c]);
            float ssw  = __fmul_rn(sr, sw[c]);
            float val  = __fadd_rn(__fmul_rn(diff, ssw), bias[c]);
            const size_t idx = (size_t)r * Nn + c;
            if (MODE == 0) outf[idx] = val;
            else if (MODE == 1) outf[idx] = gelu_xla(val);
            else if (MODE == 2) outf[idx] = __fadd_rn(outf[idx], val);
            else {
                const int b = r / CNTOK;
                float gate = __fadd_rn(sst[gidx * CC + c], t[(size_t)b * 6 * CC + gidx * CC + c]);
                fout[idx] = __fadd_rn(outf[idx], __fmul_rn(gate, val));
            }
        }
    }
}

// ---------------------------------------------------------------------------
// Quantization
// ---------------------------------------------------------------------------
__global__ void __launch_bounds__(256) quant_k(
    const float* __restrict__ X, int Kk,
    int8_t* __restrict__ Q, float* __restrict__ sOut, int* __restrict__ qsumOut)
{
    const int row = blockIdx.x, tid = threadIdx.x;
    const int lane = tid & 31, wp = tid >> 5;
    __shared__ float smA[8]; __shared__ int smI[8]; __shared__ float sSh;
    const float* xr = X + (size_t)row * Kk;

    float amax = 0.f;
    for (int i = tid; i < Kk; i += 256) amax = fmaxf(amax, fabsf(xr[i]));
    amax = warpMax(amax);
    if (lane == 0) smA[wp] = amax;
    __syncthreads();
    if (tid == 0) {
        float m = 0.f;
        #pragma unroll
        for (int i = 0; i < 8; i++) m = fmaxf(m, smA[i]);
        sSh = fmaxf(__fdiv_rn(m, 127.0f), 1e-8f);
    }
    __syncthreads();
    const float s = sSh;
    int8_t* qr = Q + (size_t)row * Kk;
    int qs = 0;
    for (int i = tid; i < Kk; i += 256) {
        float qf = rintf(__fdiv_rn(xr[i], s));
        qf = fminf(fmaxf(qf, -127.f), 127.f);
        int qi = (int)qf;
        qr[i] = (int8_t)qi;
        qs += qi;
    }
    qs = warpSumI(qs);
    if (lane == 0) smI[wp] = qs;
    __syncthreads();
    if (tid == 0) {
        int tot = 0;
        #pragma unroll
        for (int i = 0; i < 8; i++) tot += smI[i];
        sOut[row] = s; qsumOut[row] = tot;
    }
}

// ---------------------------------------------------------------------------
// QK self — smem-tiled; scores written transposed scT[k][row].
// ---------------------------------------------------------------------------
__global__ void __launch_bounds__(256) qk_self_k(
    const float* __restrict__ qkv, float* __restrict__ sc)
{
    __shared__ float Qs[64][73];
    __shared__ float Ks[64][73];
    const int qt = blockIdx.x;
    const int h  = blockIdx.y;
    const int bt = blockIdx.z;
    const int tid = threadIdx.x;
    const int tq = tid & 15;
    const int tk = tid >> 4;

    for (int idx = tid; idx < 64 * 72; idx += 256) {
        int r = idx / 72, d = idx % 72;
        Qs[r][d] = qkv[(size_t)(bt * CS + qt * 64 + r) * 3456 + h * 72 + d];
    }

    for (int kt = 0; kt < 4; kt++) {
        __syncthreads();
        for (int idx = tid; idx < 64 * 72; idx += 256) {
            int r = idx / 72, d = idx % 72;
            Ks[r][d] = qkv[(size_t)(bt * CS + kt * 64 + r) * 3456 + 1152 + h * 72 + d];
        }
        __syncthreads();

        float acc[4][4] = {};
        for (int d = 0; d < 72; d++) {
            float qsv[4], kvv[4];
            #pragma unroll
            for (int i = 0; i < 4; i++) qsv[i] = __fmul_rn(Qs[tq + i * 16][d], QSCALE_F);
            #pragma unroll
            for (int j = 0; j < 4; j++) kvv[j] = Ks[tk + j * 16][d];
            #pragma unroll
            for (int i = 0; i < 4; i++)
                #pragma unroll
                for (int j = 0; j < 4; j++)
                    acc[i][j] = __fmaf_rn(qsv[i], kvv[j], acc[i][j]);
        }
        #pragma unroll
        for (int j = 0; j < 4; j++) {
            int k = kt * 64 + tk + j * 16;
            #pragma unroll
            for (int i = 0; i < 4; i++) {
                int rowg = (bt * 16 + h) * 256 + qt * 64 + tq + i * 16;
                sc[(size_t)k * NROWS + rowg] = acc[i][j];
            }
        }
    }
}

__global__ void __launch_bounds__(256) qk_cross_k(
    const float* __restrict__ Q, const float* __restrict__ KV, float* __restrict__ sc)
{
    __shared__ float Qs[64][73];
    __shared__ float Ks[64][73];
    const int qt = blockIdx.x;
    const int h  = blockIdx.y;
    const int tid = threadIdx.x;
    const int tq = tid & 15;
    const int tk = tid >> 4;

    for (int idx = tid; idx < 64 * 72; idx += 256) {
        int r = idx / 72, d = idx % 72;
        Qs[r][d] = Q[(size_t)(qt * 64 + r) * CC + h * 72 + d];
    }

    for (int kt = 0; kt < 7; kt++) {
        __syncthreads();
        for (int idx = tid; idx < 64 * 72; idx += 256) {
            int r = idx / 72, d = idx % 72;
            Ks[r][d] = KV[(size_t)(kt * 64 + r) * 2304 + h * 72 + d];
        }
        __syncthreads();

        float acc[4][4] = {};
        for (int d = 0; d < 72; d++) {
            float qsv[4], kvv[4];
            #pragma unroll
            for (int i = 0; i < 4; i++) qsv[i] = __fmul_rn(Qs[tq + i * 16][d], QSCALE_F);
            #pragma unroll
            for (int j = 0; j < 4; j++) kvv[j] = Ks[tk + j * 16][d];
            #pragma unroll
            for (int i = 0; i < 4; i++)
                #pragma unroll
                for (int j = 0; j < 4; j++)
                    acc[i][j] = __fmaf_rn(qsv[i], kvv[j], acc[i][j]);
        }
        #pragma unroll
        for (int j = 0; j < 4; j++) {
            int k = kt * 64 + tk + j * 16;
            #pragma unroll
            for (int i = 0; i < 4; i++) {
                int rowg = h * 4096 + qt * 64 + tq + i * 16;
                sc[(size_t)k * NROWS + rowg] = acc[i][j];
            }
        }
    }
}

// ---------------------------------------------------------------------------
// Softmax — 4 rows per thread (float4 across adjacent rows); per-row chains
// bit-identical to the scalar version.
// ---------------------------------------------------------------------------
__global__ void __launch_bounds__(256) softmax_mimic_k(
    float* __restrict__ sc, int rows4, int len)
{
    int r4 = blockIdx.x * 256 + threadIdx.x;
    if (r4 >= rows4) return;
    float* p = sc + (size_t)r4 * 4;

    float4 mx = make_float4(-INFINITY, -INFINITY, -INFINITY, -INFINITY);
    for (int i = 0; i < len; i++) {
        float4 v = *(const float4*)&p[(size_t)i * NROWS];
        mx.x = fmaxf(mx.x, v.x); mx.y = fmaxf(mx.y, v.y);
        mx.z = fmaxf(mx.z, v.z); mx.w = fmaxf(mx.w, v.w);
    }
    float a[4][4];   // [row][chain]
    #pragma unroll
    for (int r = 0; r < 4; r++)
        #pragma unroll
        for (int l = 0; l < 4; l++) a[r][l] = 0.f;
    for (int i = 0; i < len; i += 4) {
        #pragma unroll
        for (int l = 0; l < 4; l++) {
            float4 v = *(const float4*)&p[(size_t)(i + l) * NROWS];
            float4 e;
            e.x = xla_expf(__fsub_rn(v.x, mx.x));
            e.y = xla_expf(__fsub_rn(v.y, mx.y));
            e.z = xla_expf(__fsub_rn(v.z, mx.z));
            e.w = xla_expf(__fsub_rn(v.w, mx.w));
            *(float4*)&p[(size_t)(i + l) * NROWS] = e;
            a[0][l] = __fadd_rn(a[0][l], e.x);
            a[1][l] = __fadd_rn(a[1][l], e.y);
            a[2][l] = __fadd_rn(a[2][l], e.z);
            a[3][l] = __fadd_rn(a[3][l], e.w);
        }
    }
    float4 sum;
    sum.x = combine4p(a[0]); sum.y = combine4p(a[1]);
    sum.z = combine4p(a[2]); sum.w = combine4p(a[3]);
    for (int i = 0; i < len; i++) {
        float4 v = *(const float4*)&p[(size_t)i * NROWS];
        v.x = __fdiv_rn(v.x, sum.x); v.y = __fdiv_rn(v.y, sum.y);
        v.z = __fdiv_rn(v.z, sum.z); v.w = __fdiv_rn(v.w, sum.w);
        *(float4*)&p[(size_t)i * NROWS] = v;
    }
}

// ---------------------------------------------------------------------------
// PV — smem-tiled GEMM-style; chain identical (k ascending, single acc).
// ---------------------------------------------------------------------------
__global__ void __launch_bounds__(288) pv_self_k(
    const float* __restrict__ sc, const float* __restrict__ qkv, float* __restrict__ O)
{
    __shared__ float Ps[64][68];
    __shared__ float Vs[64][76];
    const int qt = blockIdx.x;
    const int h  = blockIdx.y;
    const int bt = blockIdx.z;
    const int tid = threadIdx.x;
    const int tr = tid / 18;
    const int tc = tid % 18;
    const int rowg0 = (bt * 16 + h) * 256 + qt * 64;
    const float* vbase = qkv + (size_t)bt * CS * 3456 + 2304 + h * 72;

    float acc[4][4] = {};

    for (int kt = 0; kt < 4; kt++) {
        __syncthreads();
        for (int idx = tid; idx < 64 * 64; idx += 288) {
            int k = idx >> 6, r = idx & 63;
            Ps[k][r] = sc[(size_t)(kt * 64 + k) * NROWS + rowg0 + r];
        }
        for (int idx = tid; idx < 64 * 72; idx += 288) {
            int k = idx / 72, c = idx % 72;
            Vs[k][c] = vbase[(size_t)(kt * 64 + k) * 3456 + c];
        }
        __syncthreads();

        for (int k = 0; k < 64; k++) {
            float4 p4 = *(const float4*)&Ps[k][tr * 4];
            float4 v4 = *(const float4*)&Vs[k][tc * 4];
            float pv[4] = {p4.x, p4.y, p4.z, p4.w};
            float vv[4] = {v4.x, v4.y, v4.z, v4.w};
            #pragma unroll
            for (int i = 0; i < 4; i++)
                #pragma unroll
                for (int j = 0; j < 4; j++)
                    acc[i][j] = __fmaf_rn(pv[i], vv[j], acc[i][j]);
        }
    }

    #pragma unroll
    for (int i = 0; i < 4; i++) {
        int tok = bt * CS + qt * 64 + tr * 4 + i;
        #pragma unroll
        for (int j = 0; j < 4; j++)
            O[(size_t)tok * CC + h * 72 + tc * 4 + j] = acc[i][j];
    }
}

__global__ void __launch_bounds__(288) pv_cross_k(
    const float* __restrict__ sc, const float* __restrict__ KV, float* __restrict__ O)
{
    __shared__ float Ps[64][68];
    __shared__ float Vs[64][76];
    const int qt = blockIdx.x;
    const int h  = blockIdx.y;
    const int tid = threadIdx.x;
    const int tr = tid / 18;
    const int tc = tid % 18;
    const int rowg0 = h * 4096 + qt * 64;
    const float* vbase = KV + 1152 + h * 72;

    float acc[4][4] = {};

    for (int kt = 0; kt < 7; kt++) {
        __syncthreads();
        for (int idx = tid; idx < 64 * 64; idx += 288) {
            int k = idx >> 6, r = idx & 63;
            Ps[k][r] = sc[(size_t)(kt * 64 + k) * NROWS + rowg0 + r];
        }
        for (int idx = tid; idx < 64 * 72; idx += 288) {
            int k = idx / 72, c = idx % 72;
            Vs[k][c] = vbase[(size_t)(kt * 64 + k) * 2304 + c];
        }
        __syncthreads();

        for (int k = 0; k < 64; k++) {
            float4 p4 = *(const float4*)&Ps[k][tr * 4];
            float4 v4 = *(const float4*)&Vs[k][tc * 4];
            float pv[4] = {p4.x, p4.y, p4.z, p4.w};
            float vv[4] = {v4.x, v4.y, v4.z, v4.w};
            #pragma unroll
            for (int i = 0; i < 4; i++)
                #pragma unroll
                for (int j = 0; j < 4; j++)
                    acc[i][j] = __fmaf_rn(pv[i], vv[j], acc[i][j]);
        }
    }

    #pragma unroll
    for (int i = 0; i < 4; i++) {
        int qi = qt * 64 + tr * 4 + i;
        #pragma unroll
        for (int j = 0; j < 4; j++)
            O[(size_t)qi * CC + h * 72 + tc * 4 + j] = acc[i][j];
    }
}

// ---------------------------------------------------------------------------
// Host launch
// ---------------------------------------------------------------------------
extern "C" void kernel_launch(void* const* d_in, const int* in_sizes, int n_in,
                              void* d_out, int out_size)
{
    const float* x    = (const float*)d_in[0];
    const float* y    = (const float*)d_in[1];
    const float* t    = (const float*)d_in[2];
    const float* sst  = (const float*)d_in[3];
    const float* Wqkv = (const float*)d_in[4];
    const float* bqkv = (const float*)d_in[5];
    const float* Wo   = (const float*)d_in[6];
    const float* bo   = (const float*)d_in[7];
    const float* Wkv  = (const float*)d_in[8];
    const float* bkv  = (const float*)d_in[9];
    const int*   qw_q  = (const int*)d_in[10];
    const float* sw_q  = (const float*)d_in[11];
    const int*   zw_q  = (const int*)d_in[12];
    const float* b_q   = (const float*)d_in[13];
    const int*   qw_cp = (const int*)d_in[14];
    const float* sw_cp = (const float*)d_in[15];
    const int*   zw_cp = (const int*)d_in[16];
    const float* b_cp  = (const float*)d_in[17];
    const int*   qw_f1 = (const int*)d_in[18];
    const float* sw_f1 = (const float*)d_in[19];
    const int*   zw_f1 = (const int*)d_in[20];
    const float* b_f1  = (const float*)d_in[21];
    const int*   qw_f2 = (const int*)d_in[22];
    const float* sw_f2 = (const float*)d_in[23];
    const int*   zw_f2 = (const int*)d_in[24];
    const float* b_f2  = (const float*)d_in[25];
    float* out = (float*)d_out;

    float *p_xm, *p_qkv, *p_tmp, *p_crossq, *p_kv, *p_h, *p_x, *p_sc, *p_srow;
    int *p_q8, *p_qsum, *p_wq8, *p_wcp8, *p_wf18, *p_wf28;
    cudaGetSymbolAddress((void**)&p_xm,     g_xm);
    cudaGetSymbolAddress((void**)&p_qkv,    g_qkv);
    cudaGetSymbolAddress((void**)&p_tmp,    g_tmp);
    cudaGetSymbolAddress((void**)&p_crossq, g_crossq);
    cudaGetSymbolAddress((void**)&p_kv,     g_kv);
    cudaGetSymbolAddress((void**)&p_h,      g_h);
    cudaGetSymbolAddress((void**)&p_x,      g_x);
    cudaGetSymbolAddress((void**)&p_sc,     g_sc);
    cudaGetSymbolAddress((void**)&p_q8,     g_q8);
    cudaGetSymbolAddress((void**)&p_srow,   g_srow);
    cudaGetSymbolAddress((void**)&p_qsum,   g_qsum);
    cudaGetSymbolAddress((void**)&p_wq8,    g_wq8);
    cudaGetSymbolAddress((void**)&p_wcp8,   g_wcp8);
    cudaGetSymbolAddress((void**)&p_wf18,   g_wf18);
    cudaGetSymbolAddress((void**)&p_wf28,   g_wf28);

    // 0) pack int8 weights
    {
        int n1 = CC * CC / 4;
        int n2 = CDH * CC / 4;
        pack_i8_k<<<(n1 + 255) / 256, 256>>>((const int4*)qw_q,  p_wq8,  n1);
        pack_i8_k<<<(n1 + 255) / 256, 256>>>((const int4*)qw_cp, p_wcp8, n1);
        pack_i8_k<<<(n2 + 255) / 256, 256>>>((const int4*)qw_f1, p_wf18, n2);
        pack_i8_k<<<(n2 + 255) / 256, 256>>>((const int4*)qw_f2, p_wf28, n2);
    }

    // 1) x_m = ln(x)*(1+scale_msa)+shift_msa
    ln_mod_k<<<CROWS, 256>>>(x, p_xm, t, sst, 0, 1);

    // 2) qkv = x_m @ Wqkv^T + bqkv
    gemm_f32_k<0><<<dim3(3 * CC / 64, CROWS / 128), 256>>>(
        p_xm, Wqkv, bqkv, p_qkv, 3 * CC, CC, CROWS, nullptr, nullptr, nullptr, 0);

    // 3) self attention
    qk_self_k<<<dim3(4, CH, CB * CT), 256>>>(p_qkv, p_sc);
    softmax_mimic_k<<<NROWS / 4 / 256, 256>>>(p_sc, NROWS / 4, 256);
    pv_self_k<<<dim3(4, CH, CB * CT), 288>>>(p_sc, p_qkv, p_tmp);

    // 4) x_res = x + gate_msa * (attn @ Wo^T + bo)
    gemm_f32_k<1><<<dim3(CC / 64, CROWS / 128), 256>>>(
        p_tmp, Wo, bo, p_x, CC, CC, CROWS, x, t, sst, 2);

    // 5) quantize post-msa x
    quant_k<<<CROWS, 256>>>(p_x, CC, (int8_t*)p_q8, p_srow, p_qsum);

    // 6) cross-attn q = w8a8(x, qw_q,...)
    gemm_i8_k<0><<<dim3(CC / 64, CROWS / 64), 256>>>(
        p_q8, p_wq8, p_srow, p_qsum, sw_q, zw_q, b_q, p_crossq,
        CC, CC / 4, nullptr, nullptr, 0, nullptr);

    // 7) kv = y @ Wkv^T + bkv
    gemm_f32_k<0><<<dim3(2 * CC / 64, (CKVR + 127) / 128), 256>>>(
        y, Wkv, bkv, p_kv, 2 * CC, CC, CKVR, nullptr, nullptr, nullptr, 0);

    // 8) cross attention
    qk_cross_k<<<dim3(64, CH), 256>>>(p_crossq, p_kv, p_sc);
    softmax_mimic_k<<<NROWS / 4 / 256, 256>>>(p_sc, NROWS / 4, 448);
    pv_cross_k<<<dim3(64, CH), 288>>>(p_sc, p_kv, p_tmp);

    // 9) quantize cross-attn output
    quant_k<<<CROWS, 256>>>(p_tmp, CC, (int8_t*)p_q8, p_srow, p_qsum);

    // 10) x_res += w8a8(cross_out, qw_cp,...)
    gemm_i8_k<2><<<dim3(CC / 64, CROWS / 64), 256>>>(
        p_q8, p_wcp8, p_srow, p_qsum, sw_cp, zw_cp, b_cp, p_x,
        CC, CC / 4, nullptr, nullptr, 0, nullptr);

    // 11) x_m = ln(x_res)*(1+scale_mlp)+shift_mlp
    ln_mod_k<<<CROWS, 256>>>(p_x, p_xm, t, sst, 3, 4);

    // 12) quantize x_m
    quant_k<<<CROWS, 256>>>(p_xm, CC, (int8_t*)p_q8, p_srow, p_qsum);

    // 13) h = gelu(w8a8(x_m, qw_f1,...))
    gemm_i8_k<1><<<dim3(CDH / 64, CROWS / 64), 256>>>(
        p_q8, p_wf18, p_srow, p_qsum, sw_f1, zw_f1, b_f1, p_h,
        CDH, CC / 4, nullptr, nullptr, 0, nullptr);

    // 14) quantize h
    quant_k<<<CROWS, 256>>>(p_h, CDH, (int8_t*)p_q8, p_srow, p_qsum);

    // 15) out = x_res + gate_mlp * w8a8(h, qw_f2,...)
    gemm_i8_k<3><<<dim3(CC / 64, CROWS / 64), 256>>>(
        p_q8, p_wf28, p_srow, p_qsum, sw_f2, zw_f2, b_f2, p_x,
        CC, CDH / 4, t, sst, 5, out);
}

// round 17
// speedup vs baseline: 1.1927x; 1.1927x over previous
#include <cuda_runtime.h>
#include <cstdint>
#include <math.h>

// ---------------------------------------------------------------------------
// Problem constants
// ---------------------------------------------------------------------------
namespace {
constexpr int CB     = 2;
constexpr int CT     = 8;
constexpr int CS     = 256;
constexpr int CNTOK  = CT * CS;      // 2048
constexpr int CROWS  = CB * CNTOK;   // 4096
constexpr int CC     = 1152;
constexpr int CH     = 16;
constexpr int CHD    = 72;
constexpr int CM     = 224;
constexpr int CKVR   = CB * CM;      // 448
constexpr int CDH    = 4608;
constexpr int KC     = 504;          // Eigen kc panel (aarch64 L1=32KB default)
constexpr int NROWS  = CROWS * CH;   // 65536 attention rows
}
#define QSCALE_F  0.117851130664348602294921875f   /* fl32(72**-0.5) */
#define SQ2OPI_F  0.797884583473205566406250f      /* fl32(np.sqrt(2/np.pi)) */

// ---------------------------------------------------------------------------
// Scratch
// ---------------------------------------------------------------------------
__device__ float g_xm[CROWS * CC];
__device__ float g_qkv[CROWS * 3 * CC];
__device__ float g_tmp[CROWS * CC];
__device__ float g_crossq[CROWS * CC];
__device__ float g_kv[CKVR * 2 * CC];
__device__ float g_h[CROWS * CDH];
__device__ float g_x[CROWS * CC];
__device__ float g_sc[(size_t)NROWS * CKVR];      // scores, TRANSPOSED [k][row]
__device__ int   g_q8[CROWS * CDH / 4];
__device__ float g_srow[CROWS];
__device__ int   g_qsum[CROWS];
__device__ int   g_wq8 [CC * CC / 4];
__device__ int   g_wcp8[CC * CC / 4];
__device__ int   g_wf18[CDH * CC / 4];
__device__ int   g_wf28[CC * CDH / 4];

// ---------------------------------------------------------------------------
// XLA:CPU bit-mimicry helpers
// ---------------------------------------------------------------------------
__device__ __forceinline__ float xla_expf(float x) {
    float xc = fminf(x, 88.3762626647950f);
    xc = fmaxf(xc, -88.3762626647949f);
    float fx = __fadd_rn(__fmul_rn(xc, 1.44269504088896341f), 0.5f);
    fx = floorf(fx);
    float tmp = __fmul_rn(fx, 0.693359375f);
    float z2  = __fmul_rn(fx, -2.12194440e-4f);
    float xr  = __fsub_rn(xc, tmp);
    xr = __fsub_rn(xr, z2);
    float zz = __fmul_rn(xr, xr);
    float y = 1.9875691500E-4f;
    y = __fadd_rn(__fmul_rn(y, xr), 1.3981999507E-3f);
    y = __fadd_rn(__fmul_rn(y, xr), 8.3334519073E-3f);
    y = __fadd_rn(__fmul_rn(y, xr), 4.1665795894E-2f);
    y = __fadd_rn(__fmul_rn(y, xr), 1.6666665459E-1f);
    y = __fadd_rn(__fmul_rn(y, xr), 5.0000001201E-1f);
    y = __fadd_rn(__fmul_rn(y, zz), xr);
    y = __fadd_rn(y, 1.0f);
    int n = (int)fx;
    float p2n = __uint_as_float((unsigned)(n + 127) << 23);
    return __fmul_rn(y, p2n);
}

__device__ __forceinline__ float xla_tanh(float x) {
    if (fabsf(x) < 0.0004f) return x;
    float xc = fminf(fmaxf(x, -7.90531110763549805f), 7.90531110763549805f);
    float x2 = __fmul_rn(xc, xc);
    float p = -2.76076847742355e-16f;
    p = __fadd_rn(__fmul_rn(x2, p),  2.00018790482477e-13f);
    p = __fadd_rn(__fmul_rn(x2, p), -8.60467152213735e-11f);
    p = __fadd_rn(__fmul_rn(x2, p),  5.12229709037114e-08f);
    p = __fadd_rn(__fmul_rn(x2, p),  1.48572235717979e-05f);
    p = __fadd_rn(__fmul_rn(x2, p),  6.37261928875436e-04f);
    p = __fadd_rn(__fmul_rn(x2, p),  4.89352455891786e-03f);
    float num = __fmul_rn(xc, p);
    float q = __fadd_rn(__fmul_rn(x2, 1.19825839466702e-06f), 1.18534705686654e-04f);
    q = __fadd_rn(__fmul_rn(x2, q), 2.26843463243900e-03f);
    q = __fadd_rn(__fmul_rn(x2, q), 4.89352518554385e-03f);
    return __fdiv_rn(num, q);
}

__device__ __forceinline__ float gelu_xla(float v) {
    float v2 = __fmul_rn(v, v);
    float v3 = __fmul_rn(v2, v);
    float inner = __fadd_rn(v, __fmul_rn(0.044715f, v3));
    float u = __fmul_rn(SQ2OPI_F, inner);
    float th = xla_tanh(u);
    return __fmul_rn(__fmul_rn(0.5f, v), __fadd_rn(1.0f, th));
}

__device__ __forceinline__ float combine4p(const float* c) {
    return __fadd_rn(__fadd_rn(c[0], c[1]), __fadd_rn(c[2], c[3]));
}

__device__ __forceinline__ float warpMax(float v) {
    #pragma unroll
    for (int o = 16; o; o >>= 1) v = fmaxf(v, __shfl_xor_sync(0xffffffffu, v, o));
    return v;
}
__device__ __forceinline__ double warpSumD(double v) {
    #pragma unroll
    for (int o = 16; o; o >>= 1) v += __shfl_xor_sync(0xffffffffu, v, o);
    return v;
}
__device__ __forceinline__ int warpSumI(int v) {
    #pragma unroll
    for (int o = 16; o; o >>= 1) v += __shfl_xor_sync(0xffffffffu, v, o);
    return v;
}

__device__ __forceinline__ void mma_s8(
    int& d0, int& d1, int& d2, int& d3,
    int a0, int a1, int a2, int a3, int b0, int b1)
{
    asm volatile(
        "mma.sync.aligned.m16n8k32.row.col.s32.s8.s8.s32 "
        "{%0,%1,%2,%3}, {%4,%5,%6,%7}, {%8,%9}, {%0,%1,%2,%3};"
        : "+r"(d0), "+r"(d1), "+r"(d2), "+r"(d3)
        : "r"(a0), "r"(a1), "r"(a2), "r"(a3), "r"(b0), "r"(b1));
}

// ---------------------------------------------------------------------------
// Pack int32-widened int8 weights into packed int8 words
// ---------------------------------------------------------------------------
__global__ void __launch_bounds__(256) pack_i8_k(
    const int4* __restrict__ W32, int* __restrict__ W8, int n4)
{
    int i = blockIdx.x * 256 + threadIdx.x;
    if (i < n4) {
        int4 v = W32[i];
        unsigned w = (unsigned)(v.x & 0xff)
                   | ((unsigned)(v.y & 0xff) << 8)
                   | ((unsigned)(v.z & 0xff) << 16)
                   | ((unsigned)(v.w & 0xff) << 24);
        W8[i] = (int)w;
    }
}

// ---------------------------------------------------------------------------
// LayerNorm + adaLN modulate — fp64-exact stats, fp32 modulate (unfused).
// ---------------------------------------------------------------------------
__global__ void __launch_bounds__(256) ln_mod_k(
    const float* __restrict__ X, float* __restrict__ out,
    const float* __restrict__ t, const float* __restrict__ sst,
    int shidx, int scidx)
{
    const int row = blockIdx.x, tid = threadIdx.x;
    const int lane = tid & 31, wp = tid >> 5;
    const int b = row / CNTOK;
    const float* xr = X + (size_t)row * CC;
    __shared__ double smA[8];
    __shared__ float stats[2];

    double s1 = 0.0;
    for (int i = tid; i < CC; i += 256) s1 += (double)xr[i];
    s1 = warpSumD(s1);
    if (lane == 0) smA[wp] = s1;
    __syncthreads();
    if (tid == 0) {
        double a = 0.0;
        #pragma unroll
        for (int i = 0; i < 8; i++) a += smA[i];
        stats[0] = (float)(a / 1152.0);
    }
    __syncthreads();
    const float meanf = stats[0];

    double s2 = 0.0;
    for (int i = tid; i < CC; i += 256) {
        double d = (double)xr[i] - (double)meanf;
        s2 += d * d;
    }
    s2 = warpSumD(s2);
    if (lane == 0) smA[wp] = s2;
    __syncthreads();
    if (tid == 0) {
        double c2 = 0.0;
        #pragma unroll
        for (int i = 0; i < 8; i++) c2 += smA[i];
        float varf = (float)(c2 / 1152.0);
        stats[1] = __fdiv_rn(1.0f, __fsqrt_rn(__fadd_rn(varf, 1e-6f)));
    }
    __syncthreads();
    const float rstd = stats[1];
    const float* tb = t + (size_t)b * 6 * CC;
    for (int i = tid; i < CC; i += 256) {
        float sc = __fadd_rn(1.0f, __fadd_rn(sst[scidx * CC + i], tb[scidx * CC + i]));
        float sh = __fadd_rn(sst[shidx * CC + i], tb[shidx * CC + i]);
        float ln = __fmul_rn(__fsub_rn(xr[i], meanf), rstd);
        out[(size_t)row * CC + i] = __fadd_rn(__fmul_rn(ln, sc), sh);   // unfused
    }
}

// ---------------------------------------------------------------------------
// fp32 GEMM — 128x64 tile, 8x4 microtile, Eigen kc=504 panel folds.
// ---------------------------------------------------------------------------
template<int MODE>
__global__ void __launch_bounds__(256) gemm_f32_k(
    const float* __restrict__ A, const float* __restrict__ W,
    const float* __restrict__ bias, float* __restrict__ out,
    int Nn, int Kk, int Mrows,
    const float* __restrict__ xsrc, const float* __restrict__ t,
    const float* __restrict__ sst, int gidx)
{
    __shared__ float As[16][128];
    __shared__ float Ws[16][64];
    const int tid = threadIdx.x;
    const int tx = tid & 15;
    const int ty = tid >> 4;
    const int rowbase = blockIdx.y * 128;
    const int colbase = blockIdx.x * 64;
    const int lr = tid >> 1;
    const int lk = (tid & 1) * 8;
    const int wr = tid >> 2;
    const int wk = (tid & 3) * 4;
    const int ar_g = (rowbase + lr < Mrows) ? (rowbase + lr) : (Mrows - 1);
    const float* Ap = A + (size_t)ar_g * Kk;
    const float* Wp = W + (size_t)(colbase + wr) * Kk;
    float acc[8][4] = {};
    float tot[8][4] = {};

    for (int k0 = 0; k0 < Kk; k0 += 16) {
        float4 a0 = *(const float4*)(Ap + k0 + lk);
        float4 a1 = *(const float4*)(Ap + k0 + lk + 4);
        float4 wv = *(const float4*)(Wp + k0 + wk);
        As[lk + 0][lr] = a0.x; As[lk + 1][lr] = a0.y;
        As[lk + 2][lr] = a0.z; As[lk + 3][lr] = a0.w;
        As[lk + 4][lr] = a1.x; As[lk + 5][lr] = a1.y;
        As[lk + 6][lr] = a1.z; As[lk + 7][lr] = a1.w;
        Ws[wk + 0][wr] = wv.x; Ws[wk + 1][wr] = wv.y;
        Ws[wk + 2][wr] = wv.z; Ws[wk + 3][wr] = wv.w;
        __syncthreads();
        #pragma unroll
        for (int kk = 0; kk < 16; kk++) {
            int kg = k0 + kk;
            if (kg == KC || kg == 2 * KC) {      // Eigen panel boundary
                #pragma unroll
                for (int i = 0; i < 8; i++)
                    #pragma unroll
                    for (int j = 0; j < 4; j++) {
                        tot[i][j] = __fadd_rn(tot[i][j], acc[i][j]);
                        acc[i][j] = 0.f;
                    }
            }
            float4 aa0 = *(const float4*)&As[kk][ty * 8];
            float4 aa1 = *(const float4*)&As[kk][ty * 8 + 4];
            float4 ww  = *(const float4*)&Ws[kk][tx * 4];
            float ar[8] = {aa0.x, aa0.y, aa0.z, aa0.w, aa1.x, aa1.y, aa1.z, aa1.w};
            float wr4[4] = {ww.x, ww.y, ww.z, ww.w};
            #pragma unroll
            for (int i = 0; i < 8; i++)
                #pragma unroll
                for (int j = 0; j < 4; j++)
                    acc[i][j] = __fmaf_rn(ar[i], wr4[j], acc[i][j]);
        }
        __syncthreads();
    }

    #pragma unroll
    for (int i = 0; i < 8; i++) {
        const int r = rowbase + ty * 8 + i;
        if (r >= Mrows) continue;
        #pragma unroll
        for (int j = 0; j < 4; j++) {
            const int c = colbase + tx * 4 + j;
            float accv = __fadd_rn(tot[i][j], acc[i][j]);
            float v = __fadd_rn(accv, bias[c]);
            const size_t idx = (size_t)r * Nn + c;
            if (MODE == 0) {
                out[idx] = v;
            } else {
                const int b = r / CNTOK;
                float gate = __fadd_rn(sst[gidx * CC + c], t[(size_t)b * 6 * CC + gidx * CC + c]);
                out[idx] = __fadd_rn(xsrc[idx], __fmul_rn(gate, v));   // unfused
            }
        }
    }
}

// ---------------------------------------------------------------------------
// int8 GEMM via IMMA, double-buffered smem, k-step 16 words (64 int8).
// Integer accumulation — order irrelevant, exact.
// ---------------------------------------------------------------------------
template<int MODE>
__global__ void __launch_bounds__(256) gemm_i8_k(
    const int* __restrict__ A, const int* __restrict__ W,
    const float* __restrict__ srow, const int* __restrict__ qsum,
    const float* __restrict__ sw, const int* __restrict__ zw,
    const float* __restrict__ bias, float* __restrict__ outf,
    int Nn, int Kw,
    const float* __restrict__ t, const float* __restrict__ sst, int gidx,
    float* __restrict__ fout)
{
    __shared__ int As[2][64][20];   // stride 20: conflict-free fragment loads
    __shared__ int Ws[2][64][20];
    const int tid = threadIdx.x;
    const int rowbase = blockIdx.y * 64;
    const int colbase = blockIdx.x * 64;
    const int warp = tid >> 5;
    const int lane = tid & 31;
    const int wm = warp & 3;
    const int wn = warp >> 2;
    const int g  = lane >> 2;
    const int tg = lane & 3;
    const int lr = tid >> 2;          // 0..63
    const int lq = (tid & 3) * 4;     // 0,4,8,12
    const int* ArP = A + (size_t)(rowbase + lr) * Kw + lq;
    const int* WrP = W + (size_t)(colbase + lr) * Kw + lq;

    int acc[4][4] = {};
    const int nIter = Kw / 16;

    *(int4*)&As[0][lr][lq] = *(const int4*)ArP;
    *(int4*)&Ws[0][lr][lq] = *(const int4*)WrP;
    __syncthreads();

    for (int it = 0; it < nIter; it++) {
        const int buf = it & 1;
        if (it + 1 < nIter) {
            const int kw = (it + 1) * 16;
            *(int4*)&As[buf ^ 1][lr][lq] = *(const int4*)(ArP + kw);
            *(int4*)&Ws[buf ^ 1][lr][lq] = *(const int4*)(WrP + kw);
        }
        #pragma unroll
        for (int half = 0; half < 2; half++) {
            const int o = half * 8;
            const int a0 = As[buf][wm * 16 + g    ][o + tg];
            const int a1 = As[buf][wm * 16 + g + 8][o + tg];
            const int a2 = As[buf][wm * 16 + g    ][o + 4 + tg];
            const int a3 = As[buf][wm * 16 + g + 8][o + 4 + tg];
            #pragma unroll
            for (int j = 0; j < 4; j++) {
                const int n = wn * 32 + j * 8;
                const int b0 = Ws[buf][n + g][o + tg];
                const int b1 = Ws[buf][n + g][o + 4 + tg];
                mma_s8(acc[j][0], acc[j][1], acc[j][2], acc[j][3],
                       a0, a1, a2, a3, b0, b1);
            }
        }
        __syncthreads();
    }

    #pragma unroll
    for (int j = 0; j < 4; j++) {
        #pragma unroll
        for (int f = 0; f < 4; f++) {
            const int r = rowbase + wm * 16 + g + ((f >> 1) * 8);
            const int c = colbase + wn * 32 + j * 8 + tg * 2 + (f & 1);
            const float sr = srow[r];
            const int   qr = qsum[r];
            float diff = (float)(acc[j][f] - qr * zw[c]);
            float ssw  = __fmul_rn(sr, sw[c]);
            float val  = __fadd_rn(__fmul_rn(diff, ssw), bias[c]);
            const size_t idx = (size_t)r * Nn + c;
            if (MODE == 0) outf[idx] = val;
            else if (MODE == 1) outf[idx] = gelu_xla(val);
            else if (MODE == 2) outf[idx] = __fadd_rn(outf[idx], val);
            else {
                const int b = r / CNTOK;
                float gate = __fadd_rn(sst[gidx * CC + c], t[(size_t)b * 6 * CC + gidx * CC + c]);
                fout[idx] = __fadd_rn(outf[idx], __fmul_rn(gate, val));
            }
        }
    }
}

// ---------------------------------------------------------------------------
// Quantization
// ---------------------------------------------------------------------------
__global__ void __launch_bounds__(256) quant_k(
    const float* __restrict__ X, int Kk,
    int8_t* __restrict__ Q, float* __restrict__ sOut, int* __restrict__ qsumOut)
{
    const int row = blockIdx.x, tid = threadIdx.x;
    const int lane = tid & 31, wp = tid >> 5;
    __shared__ float smA[8]; __shared__ int smI[8]; __shared__ float sSh;
    const float* xr = X + (size_t)row * Kk;

    float amax = 0.f;
    for (int i = tid; i < Kk; i += 256) amax = fmaxf(amax, fabsf(xr[i]));
    amax = warpMax(amax);
    if (lane == 0) smA[wp] = amax;
    __syncthreads();
    if (tid == 0) {
        float m = 0.f;
        #pragma unroll
        for (int i = 0; i < 8; i++) m = fmaxf(m, smA[i]);
        sSh = fmaxf(__fdiv_rn(m, 127.0f), 1e-8f);
    }
    __syncthreads();
    const float s = sSh;
    int8_t* qr = Q + (size_t)row * Kk;
    int qs = 0;
    for (int i = tid; i < Kk; i += 256) {
        float qf = rintf(__fdiv_rn(xr[i], s));
        qf = fminf(fmaxf(qf, -127.f), 127.f);
        int qi = (int)qf;
        qr[i] = (int8_t)qi;
        qs += qi;
    }
    qs = warpSumI(qs);
    if (lane == 0) smI[wp] = qs;
    __syncthreads();
    if (tid == 0) {
        int tot = 0;
        #pragma unroll
        for (int i = 0; i < 8; i++) tot += smI[i];
        sOut[row] = s; qsumOut[row] = tot;
    }
}

// ---------------------------------------------------------------------------
// QK self — smem-tiled; scores written transposed scT[k][row].
// ---------------------------------------------------------------------------
__global__ void __launch_bounds__(256) qk_self_k(
    const float* __restrict__ qkv, float* __restrict__ sc)
{
    __shared__ float Qs[64][73];
    __shared__ float Ks[64][73];
    const int qt = blockIdx.x;
    const int h  = blockIdx.y;
    const int bt = blockIdx.z;
    const int tid = threadIdx.x;
    const int tq = tid & 15;
    const int tk = tid >> 4;

    for (int idx = tid; idx < 64 * 72; idx += 256) {
        int r = idx / 72, d = idx % 72;
        Qs[r][d] = qkv[(size_t)(bt * CS + qt * 64 + r) * 3456 + h * 72 + d];
    }

    for (int kt = 0; kt < 4; kt++) {
        __syncthreads();
        for (int idx = tid; idx < 64 * 72; idx += 256) {
            int r = idx / 72, d = idx % 72;
            Ks[r][d] = qkv[(size_t)(bt * CS + kt * 64 + r) * 3456 + 1152 + h * 72 + d];
        }
        __syncthreads();

        float acc[4][4] = {};
        for (int d = 0; d < 72; d++) {
            float qsv[4], kvv[4];
            #pragma unroll
            for (int i = 0; i < 4; i++) qsv[i] = __fmul_rn(Qs[tq + i * 16][d], QSCALE_F);
            #pragma unroll
            for (int j = 0; j < 4; j++) kvv[j] = Ks[tk + j * 16][d];
            #pragma unroll
            for (int i = 0; i < 4; i++)
                #pragma unroll
                for (int j = 0; j < 4; j++)
                    acc[i][j] = __fmaf_rn(qsv[i], kvv[j], acc[i][j]);
        }
        #pragma unroll
        for (int j = 0; j < 4; j++) {
            int k = kt * 64 + tk + j * 16;
            #pragma unroll
            for (int i = 0; i < 4; i++) {
                int rowg = (bt * 16 + h) * 256 + qt * 64 + tq + i * 16;
                sc[(size_t)k * NROWS + rowg] = acc[i][j];
            }
        }
    }
}

__global__ void __launch_bounds__(256) qk_cross_k(
    const float* __restrict__ Q, const float* __restrict__ KV, float* __restrict__ sc)
{
    __shared__ float Qs[64][73];
    __shared__ float Ks[64][73];
    const int qt = blockIdx.x;
    const int h  = blockIdx.y;
    const int tid = threadIdx.x;
    const int tq = tid & 15;
    const int tk = tid >> 4;

    for (int idx = tid; idx < 64 * 72; idx += 256) {
        int r = idx / 72, d = idx % 72;
        Qs[r][d] = Q[(size_t)(qt * 64 + r) * CC + h * 72 + d];
    }

    for (int kt = 0; kt < 7; kt++) {
        __syncthreads();
        for (int idx = tid; idx < 64 * 72; idx += 256) {
            int r = idx / 72, d = idx % 72;
            Ks[r][d] = KV[(size_t)(kt * 64 + r) * 2304 + h * 72 + d];
        }
        __syncthreads();

        float acc[4][4] = {};
        for (int d = 0; d < 72; d++) {
            float qsv[4], kvv[4];
            #pragma unroll
            for (int i = 0; i < 4; i++) qsv[i] = __fmul_rn(Qs[tq + i * 16][d], QSCALE_F);
            #pragma unroll
            for (int j = 0; j < 4; j++) kvv[j] = Ks[tk + j * 16][d];
            #pragma unroll
            for (int i = 0; i < 4; i++)
                #pragma unroll
                for (int j = 0; j < 4; j++)
                    acc[i][j] = __fmaf_rn(qsv[i], kvv[j], acc[i][j]);
        }
        #pragma unroll
        for (int j = 0; j < 4; j++) {
            int k = kt * 64 + tk + j * 16;
            #pragma unroll
            for (int i = 0; i < 4; i++) {
                int rowg = h * 4096 + qt * 64 + tq + i * 16;
                sc[(size_t)k * NROWS + rowg] = acc[i][j];
            }
        }
    }
}

// ---------------------------------------------------------------------------
// Softmax on transposed scores — one row per thread (256-block grid, the
// proven round-15 configuration); coalesced, identical per-row chains.
// ---------------------------------------------------------------------------
__global__ void __launch_bounds__(256) softmax_mimic_k(
    float* __restrict__ sc, int rows, int len)
{
    int r = blockIdx.x * 256 + threadIdx.x;
    if (r >= rows) return;
    float* p = sc + r;
    float mx = -INFINITY;
    for (int i = 0; i < len; i++) mx = fmaxf(mx, p[(size_t)i * NROWS]);
    float a[4] = {0.f, 0.f, 0.f, 0.f};
    for (int i = 0; i < len; i += 4) {
        #pragma unroll
        for (int l = 0; l < 4; l++) {
            float e = xla_expf(__fsub_rn(p[(size_t)(i + l) * NROWS], mx));
            p[(size_t)(i + l) * NROWS] = e;
            a[l] = __fadd_rn(a[l], e);
        }
    }
    float sum = combine4p(a);
    for (int i = 0; i < len; i++)
        p[(size_t)i * NROWS] = __fdiv_rn(p[(size_t)i * NROWS], sum);
}

// ---------------------------------------------------------------------------
// PV — smem-tiled GEMM-style; chain identical (k ascending, single acc).
// ---------------------------------------------------------------------------
__global__ void __launch_bounds__(288) pv_self_k(
    const float* __restrict__ sc, const float* __restrict__ qkv, float* __restrict__ O)
{
    __shared__ float Ps[64][68];
    __shared__ float Vs[64][76];
    const int qt = blockIdx.x;
    const int h  = blockIdx.y;
    const int bt = blockIdx.z;
    const int tid = threadIdx.x;
    const int tr = tid / 18;
    const int tc = tid % 18;
    const int rowg0 = (bt * 16 + h) * 256 + qt * 64;
    const float* vbase = qkv + (size_t)bt * CS * 3456 + 2304 + h * 72;

    float acc[4][4] = {};

    for (int kt = 0; kt < 4; kt++) {
        __syncthreads();
        for (int idx = tid; idx < 64 * 64; idx += 288) {
            int k = idx >> 6, r = idx & 63;
            Ps[k][r] = sc[(size_t)(kt * 64 + k) * NROWS + rowg0 + r];
        }
        for (int idx = tid; idx < 64 * 72; idx += 288) {
            int k = idx / 72, c = idx % 72;
            Vs[k][c] = vbase[(size_t)(kt * 64 + k) * 3456 + c];
        }
        __syncthreads();

        for (int k = 0; k < 64; k++) {
            float4 p4 = *(const float4*)&Ps[k][tr * 4];
            float4 v4 = *(const float4*)&Vs[k][tc * 4];
            float pv[4] = {p4.x, p4.y, p4.z, p4.w};
            float vv[4] = {v4.x, v4.y, v4.z, v4.w};
            #pragma unroll
            for (int i = 0; i < 4; i++)
                #pragma unroll
                for (int j = 0; j < 4; j++)
                    acc[i][j] = __fmaf_rn(pv[i], vv[j], acc[i][j]);
        }
    }

    #pragma unroll
    for (int i = 0; i < 4; i++) {
        int tok = bt * CS + qt * 64 + tr * 4 + i;
        #pragma unroll
        for (int j = 0; j < 4; j++)
            O[(size_t)tok * CC + h * 72 + tc * 4 + j] = acc[i][j];
    }
}

__global__ void __launch_bounds__(288) pv_cross_k(
    const float* __restrict__ sc, const float* __restrict__ KV, float* __restrict__ O)
{
    __shared__ float Ps[64][68];
    __shared__ float Vs[64][76];
    const int qt = blockIdx.x;
    const int h  = blockIdx.y;
    const int tid = threadIdx.x;
    const int tr = tid / 18;
    const int tc = tid % 18;
    const int rowg0 = h * 4096 + qt * 64;
    const float* vbase = KV + 1152 + h * 72;

    float acc[4][4] = {};

    for (int kt = 0; kt < 7; kt++) {
        __syncthreads();
        for (int idx = tid; idx < 64 * 64; idx += 288) {
            int k = idx >> 6, r = idx & 63;
            Ps[k][r] = sc[(size_t)(kt * 64 + k) * NROWS + rowg0 + r];
        }
        for (int idx = tid; idx < 64 * 72; idx += 288) {
            int k = idx / 72, c = idx % 72;
            Vs[k][c] = vbase[(size_t)(kt * 64 + k) * 2304 + c];
        }
        __syncthreads();

        for (int k = 0; k < 64; k++) {
            float4 p4 = *(const float4*)&Ps[k][tr * 4];
            float4 v4 = *(const float4*)&Vs[k][tc * 4];
            float pv[4] = {p4.x, p4.y, p4.z, p4.w};
            float vv[4] = {v4.x, v4.y, v4.z, v4.w};
            #pragma unroll
            for (int i = 0; i < 4; i++)
                #pragma unroll
                for (int j = 0; j < 4; j++)
                    acc[i][j] = __fmaf_rn(pv[i], vv[j], acc[i][j]);
        }
    }

    #pragma unroll
    for (int i = 0; i < 4; i++) {
        int qi = qt * 64 + tr * 4 + i;
        #pragma unroll
        for (int j = 0; j < 4; j++)
            O[(size_t)qi * CC + h * 72 + tc * 4 + j] = acc[i][j];
    }
}

// ---------------------------------------------------------------------------
// Host launch
// ---------------------------------------------------------------------------
extern "C" void kernel_launch(void* const* d_in, const int* in_sizes, int n_in,
                              void* d_out, int out_size)
{
    const float* x    = (const float*)d_in[0];
    const float* y    = (const float*)d_in[1];
    const float* t    = (const float*)d_in[2];
    const float* sst  = (const float*)d_in[3];
    const float* Wqkv = (const float*)d_in[4];
    const float* bqkv = (const float*)d_in[5];
    const float* Wo   = (const float*)d_in[6];
    const float* bo   = (const float*)d_in[7];
    const float* Wkv  = (const float*)d_in[8];
    const float* bkv  = (const float*)d_in[9];
    const int*   qw_q  = (const int*)d_in[10];
    const float* sw_q  = (const float*)d_in[11];
    const int*   zw_q  = (const int*)d_in[12];
    const float* b_q   = (const float*)d_in[13];
    const int*   qw_cp = (const int*)d_in[14];
    const float* sw_cp = (const float*)d_in[15];
    const int*   zw_cp = (const int*)d_in[16];
    const float* b_cp  = (const float*)d_in[17];
    const int*   qw_f1 = (const int*)d_in[18];
    const float* sw_f1 = (const float*)d_in[19];
    const int*   zw_f1 = (const int*)d_in[20];
    const float* b_f1  = (const float*)d_in[21];
    const int*   qw_f2 = (const int*)d_in[22];
    const float* sw_f2 = (const float*)d_in[23];
    const int*   zw_f2 = (const int*)d_in[24];
    const float* b_f2  = (const float*)d_in[25];
    float* out = (float*)d_out;

    float *p_xm, *p_qkv, *p_tmp, *p_crossq, *p_kv, *p_h, *p_x, *p_sc, *p_srow;
    int *p_q8, *p_qsum, *p_wq8, *p_wcp8, *p_wf18, *p_wf28;
    cudaGetSymbolAddress((void**)&p_xm,     g_xm);
    cudaGetSymbolAddress((void**)&p_qkv,    g_qkv);
    cudaGetSymbolAddress((void**)&p_tmp,    g_tmp);
    cudaGetSymbolAddress((void**)&p_crossq, g_crossq);
    cudaGetSymbolAddress((void**)&p_kv,     g_kv);
    cudaGetSymbolAddress((void**)&p_h,      g_h);
    cudaGetSymbolAddress((void**)&p_x,      g_x);
    cudaGetSymbolAddress((void**)&p_sc,     g_sc);
    cudaGetSymbolAddress((void**)&p_q8,     g_q8);
    cudaGetSymbolAddress((void**)&p_srow,   g_srow);
    cudaGetSymbolAddress((void**)&p_qsum,   g_qsum);
    cudaGetSymbolAddress((void**)&p_wq8,    g_wq8);
    cudaGetSymbolAddress((void**)&p_wcp8,   g_wcp8);
    cudaGetSymbolAddress((void**)&p_wf18,   g_wf18);
    cudaGetSymbolAddress((void**)&p_wf28,   g_wf28);

    // 0) pack int8 weights
    {
        int n1 = CC * CC / 4;
        int n2 = CDH * CC / 4;
        pack_i8_k<<<(n1 + 255) / 256, 256>>>((const int4*)qw_q,  p_wq8,  n1);
        pack_i8_k<<<(n1 + 255) / 256, 256>>>((const int4*)qw_cp, p_wcp8, n1);
        pack_i8_k<<<(n2 + 255) / 256, 256>>>((const int4*)qw_f1, p_wf18, n2);
        pack_i8_k<<<(n2 + 255) / 256, 256>>>((const int4*)qw_f2, p_wf28, n2);
    }

    // 1) x_m = ln(x)*(1+scale_msa)+shift_msa
    ln_mod_k<<<CROWS, 256>>>(x, p_xm, t, sst, 0, 1);

    // 2) qkv = x_m @ Wqkv^T + bqkv
    gemm_f32_k<0><<<dim3(3 * CC / 64, CROWS / 128), 256>>>(
        p_xm, Wqkv, bqkv, p_qkv, 3 * CC, CC, CROWS, nullptr, nullptr, nullptr, 0);

    // 3) self attention
    qk_self_k<<<dim3(4, CH, CB * CT), 256>>>(p_qkv, p_sc);
    softmax_mimic_k<<<(NROWS + 255) / 256, 256>>>(p_sc, NROWS, 256);
    pv_self_k<<<dim3(4, CH, CB * CT), 288>>>(p_sc, p_qkv, p_tmp);

    // 4) x_res = x + gate_msa * (attn @ Wo^T + bo)
    gemm_f32_k<1><<<dim3(CC / 64, CROWS / 128), 256>>>(
        p_tmp, Wo, bo, p_x, CC, CC, CROWS, x, t, sst, 2);

    // 5) quantize post-msa x
    quant_k<<<CROWS, 256>>>(p_x, CC, (int8_t*)p_q8, p_srow, p_qsum);

    // 6) cross-attn q = w8a8(x, qw_q,...)
    gemm_i8_k<0><<<dim3(CC / 64, CROWS / 64), 256>>>(
        p_q8, p_wq8, p_srow, p_qsum, sw_q, zw_q, b_q, p_crossq,
        CC, CC / 4, nullptr, nullptr, 0, nullptr);

    // 7) kv = y @ Wkv^T + bkv
    gemm_f32_k<0><<<dim3(2 * CC / 64, (CKVR + 127) / 128), 256>>>(
        y, Wkv, bkv, p_kv, 2 * CC, CC, CKVR, nullptr, nullptr, nullptr, 0);

    // 8) cross attention
    qk_cross_k<<<dim3(64, CH), 256>>>(p_crossq, p_kv, p_sc);
    softmax_mimic_k<<<(NROWS + 255) / 256, 256>>>(p_sc, NROWS, 448);
    pv_cross_k<<<dim3(64, CH), 288>>>(p_sc, p_kv, p_tmp);

    // 9) quantize cross-attn output
    quant_k<<<CROWS, 256>>>(p_tmp, CC, (int8_t*)p_q8, p_srow, p_qsum);

    // 10) x_res += w8a8(cross_out, qw_cp,...)
    gemm_i8_k<2><<<dim3(CC / 64, CROWS / 64), 256>>>(
        p_q8, p_wcp8, p_srow, p_qsum, sw_cp, zw_cp, b_cp, p_x,
        CC, CC / 4, nullptr, nullptr, 0, nullptr);

    // 11) x_m = ln(x_res)*(1+scale_mlp)+shift_mlp
    ln_mod_k<<<CROWS, 256>>>(p_x, p_xm, t, sst, 3, 4);

    // 12) quantize x_m
    quant_k<<<CROWS, 256>>>(p_xm, CC, (int8_t*)p_q8, p_srow, p_qsum);

    // 13) h = gelu(w8a8(x_m, qw_f1,...))
    gemm_i8_k<1><<<dim3(CDH / 64, CROWS / 64), 256>>>(
        p_q8, p_wf18, p_srow, p_qsum, sw_f1, zw_f1, b_f1, p_h,
        CDH, CC / 4, nullptr, nullptr, 0, nullptr);

    // 14) quantize h
    quant_k<<<CROWS, 256>>>(p_h, CDH, (int8_t*)p_q8, p_srow, p_qsum);

    // 15) out = x_res + gate_mlp * w8a8(h, qw_f2,...)
    gemm_i8_k<3><<<dim3(CC / 64, CROWS / 64), 256>>>(
        p_q8, p_wf28, p_srow, p_qsum, sw_f2, zw_f2, b_f2, p_x,
        CC, CDH / 4, t, sst, 5, out);
}